// round 13
// baseline (speedup 1.0000x reference)
#include <cuda_runtime.h>
#include <cuda_bf16.h>
#include <math.h>

// Problem constants
#define BB 32
#define SS 512
#define II 512
#define HH 1024
#define OO 512
#define G4 4096          // 4*H
#define LDW 1536         // I+H, row stride of the gate weight matrices
#define NB 128           // persistent scan blocks (1 per SM, <= 148)

// packed fp32x2 FMA
#define FMA2(acc, a, b) \
    asm("fma.rn.f32x2 %0, %1, %2, %0;" : "+l"(acc) : "l"(a), "l"(b))

__device__ __forceinline__ float2 unpack2(unsigned long long v) {
    float2 r;
    asm("mov.b64 {%0, %1}, %2;" : "=f"(r.x), "=f"(r.y) : "l"(v));
    return r;
}
__device__ __forceinline__ unsigned long long dup2(float x) {
    unsigned long long r;
    asm("mov.b64 %0, {%1, %1};" : "=l"(r) : "f"(x));
    return r;
}
// cp.async.cg: 16B global->shared, L2-direct (L1 bypass) -> coherent across the
// grid barrier by construction.
__device__ __forceinline__ void cp16(unsigned dst, const void* src) {
    asm volatile("cp.async.cg.shared.global [%0], [%1], 16;" :: "r"(dst), "l"(src));
}
__device__ __forceinline__ void cp_commit() {
    asm volatile("cp.async.commit_group;");
}
template <int N> __device__ __forceinline__ void cp_wait() {
    asm volatile("cp.async.wait_group %0;" :: "n"(N));
}

// -------------------- scratch (device globals; no allocations) --------------------
__device__ float g_xg[(size_t)SS * BB * G4];   // [b][s][4H] row m = b*S+s   (256 MB)
__device__ float g_hs[(size_t)BB * SS * HH];   // [b][s][H]  row m = b*S+s   (64 MB)
__device__ float g_htA[BB * HH];               // h quad-major: [H/4][B] float4
__device__ float g_htB[BB * HH];
__device__ float g_c [BB * HH];                // c transposed: [u][b]
__device__ unsigned g_bar;                     // CG-style barrier counter

// -------------------- utility kernels --------------------
__global__ void scan_init(float* __restrict__ hA, unsigned* __restrict__ bar) {
    int i = blockIdx.x * blockDim.x + threadIdx.x;
    if (i < BB * HH) hA[i] = 0.0f;
    if (i == 0) *bar = 0u;
}

// final h quad-major [u>>2][b][u&3], c in [u][b]; emit [b][H] for both
__global__ void copy_finals(const float* __restrict__ ht, const float* __restrict__ c,
                            float* __restrict__ out) {
    int i = blockIdx.x * blockDim.x + threadIdx.x;   // i = b*HH + u
    if (i < BB * HH) {
        int b = i >> 10, u = i & (HH - 1);
        out[i]           = ht[((u >> 2) * 32 + b) * 4 + (u & 3)];
        out[BB * HH + i] = c[u * BB + b];
    }
}

// -------------------- SGEMM: C[M,N] = A[M,K] @ Bw[N,K]^T + bias[N] --------------------
// BM=BN=128, BK=16, 256 threads, 8x8 per thread. (At fp32 SIMT peak.)
__global__ __launch_bounds__(256, 2)
void sgemm_tn(int M, int N, int K,
              const float* __restrict__ A, int lda,
              const float* __restrict__ Bw, int ldb,
              const float* __restrict__ bias,
              float* __restrict__ C, int ldc) {
    __shared__ float As[16][128];
    __shared__ float Bs[16][128];

    const int tid = threadIdx.x;
    const int rowBase = blockIdx.y * 128;
    const int colBase = blockIdx.x * 128;

    const int ldRow = tid >> 2;
    const int ldK   = (tid & 3) << 2;

    const int tx = tid & 15;
    const int ty = tid >> 4;

    unsigned long long acc[8][4];
#pragma unroll
    for (int i = 0; i < 8; i++)
#pragma unroll
        for (int j = 0; j < 4; j++) acc[i][j] = 0ull;

    for (int k0 = 0; k0 < K; k0 += 16) {
#pragma unroll
        for (int r = 0; r < 128; r += 64) {
            float4 va = *reinterpret_cast<const float4*>(
                A + (size_t)(rowBase + ldRow + r) * lda + k0 + ldK);
            As[ldK + 0][ldRow + r] = va.x;
            As[ldK + 1][ldRow + r] = va.y;
            As[ldK + 2][ldRow + r] = va.z;
            As[ldK + 3][ldRow + r] = va.w;
        }
#pragma unroll
        for (int r = 0; r < 128; r += 64) {
            float4 vb = *reinterpret_cast<const float4*>(
                Bw + (size_t)(colBase + ldRow + r) * ldb + k0 + ldK);
            Bs[ldK + 0][ldRow + r] = vb.x;
            Bs[ldK + 1][ldRow + r] = vb.y;
            Bs[ldK + 2][ldRow + r] = vb.z;
            Bs[ldK + 3][ldRow + r] = vb.w;
        }
        __syncthreads();

#pragma unroll
        for (int kk = 0; kk < 16; kk++) {
            float ar[8];
#pragma unroll
            for (int i = 0; i < 8; i++) ar[i] = As[kk][ty * 8 + i];
            const ulonglong2* bp =
                reinterpret_cast<const ulonglong2*>(&Bs[kk][tx * 8]);
            ulonglong2 b01 = bp[0];
            ulonglong2 b23 = bp[1];
#pragma unroll
            for (int i = 0; i < 8; i++) {
                unsigned long long a2 = dup2(ar[i]);
                FMA2(acc[i][0], a2, b01.x);
                FMA2(acc[i][1], a2, b01.y);
                FMA2(acc[i][2], a2, b23.x);
                FMA2(acc[i][3], a2, b23.y);
            }
        }
        __syncthreads();
    }

#pragma unroll
    for (int i = 0; i < 8; i++) {
        float* crow = C + (size_t)(rowBase + ty * 8 + i) * ldc + colBase + tx * 8;
#pragma unroll
        for (int j = 0; j < 2; j++) {
            float2 p0 = unpack2(acc[i][2 * j + 0]);
            float2 p1 = unpack2(acc[i][2 * j + 1]);
            float4 v;
            v.x = p0.x + bias[colBase + tx * 8 + 4 * j + 0];
            v.y = p0.y + bias[colBase + tx * 8 + 4 * j + 1];
            v.z = p1.x + bias[colBase + tx * 8 + 4 * j + 2];
            v.w = p1.y + bias[colBase + tx * 8 + 4 * j + 3];
            *reinterpret_cast<float4*>(crow + 4 * j) = v;
        }
    }
}

// -------------------- grid-wide barrier (cooperative-groups sync_grids pattern) ----
__device__ __forceinline__ void grid_sync(unsigned* bar) {
    __syncthreads();
    if (threadIdx.x == 0) {
        __threadfence();
        unsigned add = (blockIdx.x == 0) ? (0x80000000u - (NB - 1)) : 1u;
        unsigned old = atomicAdd(bar, add);
        while (((old ^ *(volatile unsigned*)bar) & 0x80000000u) == 0u) { }
        __threadfence();
    }
    __syncthreads();
}

// -------------------- persistent recurrent scan --------------------
// 128 blocks x 256 threads, one block per SM, all 512 steps in one launch.
// Block bk owns gate-rows u in [bk*8, bk*8+8); warp w = one u (all 4 gates),
// lane = batch. Weights (128 KB) resident in smem; h staged per step through a
// cp.async.cg double-buffered pair of 32 KB chunks (64 k4-rows each):
// LDS latency (29 cyc) replaces exposed L2 latency (~260 cyc), and the block
// loads h once instead of 8x (once per warp). c stays in registers.
#define W_SMEM_FLOATS 32768          // 128 KB weights
#define HCHUNK_F4     2048           // 64 k4-rows x 32 lanes = 32 KB
#define SCAN_SMEM     (131072 + 2 * 32768)   // 192 KB

#define SCAN_FMA8()                                              \
    do {                                                          \
        FMA2(aF0, A0.x, hv.x); FMA2(aI0, A0.y, hv.x);             \
        FMA2(aO0, A1.x, hv.x); FMA2(aC0, A1.y, hv.x);             \
        FMA2(aF1, B0.x, hv.y); FMA2(aI1, B0.y, hv.y);             \
        FMA2(aO1, B1.x, hv.y); FMA2(aC1, B1.y, hv.y);             \
    } while (0)

__global__ __launch_bounds__(256, 1)
void lstm_scan(const float* __restrict__ xg,
               float* bufA, float* bufB,
               float* __restrict__ cfin, float* __restrict__ hs,
               unsigned* bar,
               const float* __restrict__ Wf, const float* __restrict__ Wi,
               const float* __restrict__ Wo, const float* __restrict__ Wc) {
    extern __shared__ float wsm[];   // [0,32768): weights; [32768,49152): h chunks
    const int tid = threadIdx.x;
    const int bk  = blockIdx.x;
    const int b   = tid & 31;        // lane = batch
    const int w   = tid >> 5;        // warp = row within block
    const int u   = bk * 8 + w;      // global gate-row

    // one-time: weights -> smem (coalesced global reads)
    for (int i = tid; i < 4 * 8 * 1024; i += 256) {
        int g  = i >> 13;            // gate
        int ww = (i >> 10) & 7;      // warp-row
        int k  = i & 1023;
        const float* Wsrc = (g == 0) ? Wf : (g == 1) ? Wi : (g == 2) ? Wo : Wc;
        float v = Wsrc[(size_t)(bk * 8 + ww) * LDW + II + k];
        wsm[(((ww * 512 + (k >> 1)) * 4 + g) << 1) + (k & 1)] = v;
    }
    __syncthreads();

    const ulonglong2* wq = reinterpret_cast<const ulonglong2*>(wsm) + (size_t)w * 1024;

    float* hsm = wsm + W_SMEM_FLOATS;              // 2 x 8192 floats
    unsigned hsm_u32;
    asm("{ .reg .u64 t; cvta.to.shared.u64 t, %1; cvt.u32.u64 %0, t; }"
        : "=r"(hsm_u32) : "l"(hsm));

    float creg = 0.0f;
    float* cur = bufA;
    float* nxt = bufB;

    for (int s = 0; s < SS; s++) {
        // prefetch this step's xg tail values (read-only data; consumed at the end)
        const float* xr = xg + ((size_t)b * SS + s) * G4;
        float xf = xr[u];
        float xi = xr[HH + u];
        float xo = xr[2 * HH + u];
        float xc = xr[3 * HH + u];

        unsigned long long aF0 = 0ull, aF1 = 0ull, aI0 = 0ull, aI1 = 0ull;
        unsigned long long aO0 = 0ull, aO1 = 0ull, aC0 = 0ull, aC1 = 0ull;

        const float4* curq = reinterpret_cast<const float4*>(cur);

        // prefetch chunk 0
#pragma unroll
        for (int k = 0; k < 8; k++)
            cp16(hsm_u32 + (unsigned)(tid + k * 256) * 16u,
                 curq + tid + k * 256);
        cp_commit();

#pragma unroll
        for (int c = 0; c < 4; c++) {
            if (c < 3) {
                unsigned dstb = hsm_u32 + (unsigned)(((c + 1) & 1) * HCHUNK_F4) * 16u;
                const float4* srcb = curq + (c + 1) * HCHUNK_F4;
#pragma unroll
                for (int k = 0; k < 8; k++)
                    cp16(dstb + (unsigned)(tid + k * 256) * 16u,
                         srcb + tid + k * 256);
                cp_commit();
                cp_wait<1>();
            } else {
                cp_wait<0>();
            }
            __syncthreads();

            const ulonglong2* hp = reinterpret_cast<const ulonglong2*>(
                hsm + (c & 1) * (HCHUNK_F4 * 4)) + b;
            const ulonglong2* wc4 = wq + c * 256;   // 64 k4 x 4 ull2 each

#pragma unroll 8
            for (int t = 0; t < 64; t++) {
                ulonglong2 hv = hp[t * 32];
                ulonglong2 A0 = wc4[t * 4 + 0];
                ulonglong2 A1 = wc4[t * 4 + 1];
                ulonglong2 B0 = wc4[t * 4 + 2];
                ulonglong2 B1 = wc4[t * 4 + 3];
                SCAN_FMA8();
            }
            __syncthreads();   // buffer (c&1) free for reuse by chunk c+2
        }

        float2 t;
        t = unpack2(aF0); float gf = t.x + t.y;
        t = unpack2(aF1); gf += t.x + t.y; gf += xf;
        t = unpack2(aI0); float gi = t.x + t.y;
        t = unpack2(aI1); gi += t.x + t.y; gi += xi;
        t = unpack2(aO0); float go = t.x + t.y;
        t = unpack2(aO1); go += t.x + t.y; go += xo;
        t = unpack2(aC0); float gc = t.x + t.y;
        t = unpack2(aC1); gc += t.x + t.y; gc += xc;

        float f  = 1.0f / (1.0f + expf(-gf));
        float ig = 1.0f / (1.0f + expf(-gi));
        float og = 1.0f / (1.0f + expf(-go));

        float cn = f * creg + ig * tanhf(gc);
        creg = cn;
        float hn = og * tanhf(cn);

        // h_next in quad-major layout + hs in [b][s][H]
        nxt[((u >> 2) * 32 + b) * 4 + (u & 3)] = hn;
        hs[((size_t)b * SS + s) * HH + u] = hn;

        grid_sync(bar);

        float* tmp = cur; cur = nxt; nxt = tmp;
    }
    // after 512 steps (even count) final h sits in bufA; write final c
    cfin[u * BB + b] = creg;
}

// -------------------- launch --------------------
extern "C" void kernel_launch(void* const* d_in, const int* in_sizes, int n_in,
                              void* d_out, int out_size) {
    (void)in_sizes; (void)n_in;
    const float* x    = (const float*)d_in[0];
    const float* Wf_w = (const float*)d_in[1];
    const float* Wf_b = (const float*)d_in[2];
    const float* Wi_w = (const float*)d_in[3];
    const float* Wi_b = (const float*)d_in[4];
    const float* Wo_w = (const float*)d_in[5];
    const float* Wo_b = (const float*)d_in[6];
    const float* Wc_w = (const float*)d_in[7];
    const float* Wc_b = (const float*)d_in[8];
    const float* out_w = (const float*)d_in[9];
    const float* out_b = (const float*)d_in[10];

    float *xg, *hs, *hA, *hB, *c;
    unsigned* bar;
    cudaGetSymbolAddress((void**)&xg, g_xg);
    cudaGetSymbolAddress((void**)&hs, g_hs);
    cudaGetSymbolAddress((void**)&hA, g_htA);
    cudaGetSymbolAddress((void**)&hB, g_htB);
    cudaGetSymbolAddress((void**)&c,  g_c);
    cudaGetSymbolAddress((void**)&bar, g_bar);

    cudaFuncSetAttribute(lstm_scan, cudaFuncAttributeMaxDynamicSharedMemorySize, SCAN_SMEM);

    // reset h0 and barrier counter (deterministic across graph replays)
    scan_init<<<128, 256>>>(hA, bar);

    const int M = BB * SS;  // 16384, row m = b*S+s

    // phase 1: xg[m][g] = x @ Wx^T + b   (4 gate GEMMs: N=1024, K=512)
    {
        dim3 grid(HH / 128, M / 128);
        sgemm_tn<<<grid, 256>>>(M, HH, II, x, II, Wf_w, LDW, Wf_b, xg + 0 * HH, G4);
        sgemm_tn<<<grid, 256>>>(M, HH, II, x, II, Wi_w, LDW, Wi_b, xg + 1 * HH, G4);
        sgemm_tn<<<grid, 256>>>(M, HH, II, x, II, Wo_w, LDW, Wo_b, xg + 2 * HH, G4);
        sgemm_tn<<<grid, 256>>>(M, HH, II, x, II, Wc_w, LDW, Wc_b, xg + 3 * HH, G4);
    }

    // phase 2: ONE persistent launch for all 512 steps
    lstm_scan<<<NB, 256, SCAN_SMEM>>>(xg, hA, hB, c, hs, bar,
                                      Wf_w, Wi_w, Wo_w, Wc_w);

    // phase 3: final = hs @ out_w^T + out_b  (M=16384, N=512, K=1024)
    {
        dim3 grid(OO / 128, M / 128);
        sgemm_tn<<<grid, 256>>>(M, OO, HH, hs, HH, out_w, HH, out_b, (float*)d_out, OO);
    }

    // tail outputs (h_fin, c_fin) if the flattened output includes them
    long long need = (long long)BB * SS * OO + 2LL * BB * HH;
    if ((long long)out_size >= need) {
        copy_finals<<<128, 256>>>(hA, c, (float*)d_out + (size_t)BB * SS * OO);
    }
}